// round 16
// baseline (speedup 1.0000x reference)
#include <cuda_runtime.h>
#include <cuda_bf16.h>
#include <math.h>
#include <stdint.h>

#define N   16384
#define D   768
#define DH  384
#define BM  128
#define NB  (N / BM)                 // 128
#define NTILES (NB * (NB + 1) / 2)   // 8256
#define BK  64
#define NSTEP (D / BK)               // 12

// smem tile: 128 rows x 128 B data, pitch 144 B -> conflict-free ldmatrix
#define LDT 144
#define TILE_BYTES (128 * LDT)              // 18432
#define BUF_BYTES  (2 * TILE_BYTES)         // A+B = 36864
#define NSTAGE 2
#define SMEM_TOTAL (NSTAGE * BUF_BYTES)     // 73728

// ---- device globals (allocation-free scratch) ----
__device__ __nv_bfloat16      g_xb[(size_t)N * D];   // bf16 row-major (24 MB)
__device__ unsigned long long g_best[N];

__device__ __forceinline__ uint32_t smem_u32(const void* p) {
    uint32_t a;
    asm("{ .reg .u64 t; cvta.to.shared.u64 t, %1; cvt.u32.u64 %0, t; }" : "=r"(a) : "l"(p));
    return a;
}
__device__ __forceinline__ unsigned f2s(float f) {
    unsigned u = __float_as_uint(f);
    return u ^ ((u & 0x80000000u) ? 0xFFFFFFFFu : 0x80000000u);
}
__device__ __forceinline__ float s2f(unsigned s) {
    unsigned u = (s & 0x80000000u) ? (s ^ 0x80000000u) : ~s;
    return __uint_as_float(u);
}
__device__ __forceinline__ void cp16(uint32_t s, const void* g) {
    asm volatile("cp.async.cg.shared.global [%0], [%1], 16;" :: "r"(s), "l"(g) : "memory");
}
__device__ __forceinline__ void cp_commit() {
    asm volatile("cp.async.commit_group;" ::: "memory");
}
template <int K>
__device__ __forceinline__ void cp_wait() {
    asm volatile("cp.async.wait_group %0;" :: "n"(K) : "memory");
}
__device__ __forceinline__ void ldm_x4(uint32_t& r0, uint32_t& r1, uint32_t& r2, uint32_t& r3,
                                       uint32_t addr) {
    asm volatile("ldmatrix.sync.aligned.m8n8.x4.shared.b16 {%0,%1,%2,%3}, [%4];"
                 : "=r"(r0), "=r"(r1), "=r"(r2), "=r"(r3) : "r"(addr));
}
__device__ __forceinline__ void mma_bf16(float* d, const uint32_t* a, const uint32_t* b) {
    asm volatile(
        "mma.sync.aligned.m16n8k16.row.col.f32.bf16.bf16.f32 "
        "{%0,%1,%2,%3}, {%4,%5,%6,%7}, {%8,%9}, {%0,%1,%2,%3};"
        : "+f"(d[0]), "+f"(d[1]), "+f"(d[2]), "+f"(d[3])
        : "r"(a[0]), "r"(a[1]), "r"(a[2]), "r"(a[3]), "r"(b[0]), "r"(b[1]));
}
__device__ __forceinline__ unsigned long long pmax(unsigned long long a, unsigned long long b) {
    return a > b ? a : b;
}

// ---------------------------------------------------------------------------
// Kernel 1: concat + L2 normalize -> bf16 g_xb. One WARP per row, no barriers.
// ---------------------------------------------------------------------------
__global__ void __launch_bounds__(256) normalize_kernel(const float* __restrict__ a,
                                                        const float* __restrict__ b) {
    int lane = threadIdx.x & 31;
    int wid  = threadIdx.x >> 5;
    int r = blockIdx.x * 8 + wid;

    const float4* A = (const float4*)(a + (size_t)r * DH);
    const float4* B = (const float4*)(b + (size_t)r * DH);
    float4 va[3], vb[3];
    float ss = 0.f;
#pragma unroll
    for (int p = 0; p < 3; p++) {
        va[p] = A[lane + 32 * p];
        vb[p] = B[lane + 32 * p];
        ss += va[p].x * va[p].x + va[p].y * va[p].y +
              va[p].z * va[p].z + va[p].w * va[p].w;
        ss += vb[p].x * vb[p].x + vb[p].y * vb[p].y +
              vb[p].z * vb[p].z + vb[p].w * vb[p].w;
    }
#pragma unroll
    for (int o = 16; o > 0; o >>= 1)
        ss += __shfl_xor_sync(0xffffffffu, ss, o);
    float inv = 1.0f / fmaxf(sqrtf(ss), 1e-8f);

    uint2* dst = (uint2*)(g_xb + (size_t)r * D);   // 4 bf16 per uint2
#pragma unroll
    for (int p = 0; p < 3; p++) {
        uint2 u;
        __nv_bfloat162* ph = (__nv_bfloat162*)&u;
        ph[0] = __floats2bfloat162_rn(va[p].x * inv, va[p].y * inv);
        ph[1] = __floats2bfloat162_rn(va[p].z * inv, va[p].w * inv);
        dst[lane + 32 * p] = u;
        uint2 w;
        __nv_bfloat162* qh = (__nv_bfloat162*)&w;
        qh[0] = __floats2bfloat162_rn(vb[p].x * inv, vb[p].y * inv);
        qh[1] = __floats2bfloat162_rn(vb[p].z * inv, vb[p].w * inv);
        dst[96 + lane + 32 * p] = w;
    }
    if (lane == 0) g_best[r] = 0ull;
}

// ---------------------------------------------------------------------------
// Kernel 2: bf16 HMMA (f32 acc) 128x128x768 tile GEMM + fused dual argmax.
// 8 warps (32x64 per warp), BK=64, 2-stage, one barrier per k-step,
// 2 CTAs/SM, triangular grid. (structure of the 586 us best; fills now .cg)
// ---------------------------------------------------------------------------
__global__ void __launch_bounds__(256, 2) gemm_argmax_hmma() {
    extern __shared__ char smem[];

    // map linear tile id -> upper-triangle (bi, bj)
    int t0 = blockIdx.x;
    int bi = (int)floorf((2.0f * NB + 1.0f -
              sqrtf((2.0f * NB + 1.0f) * (2.0f * NB + 1.0f) - 8.0f * (float)t0)) * 0.5f);
    while ((bi + 1) * NB - ((bi + 1) * bi) / 2 <= t0) bi++;
    while (bi * NB - (bi * (bi - 1)) / 2 > t0) bi--;
    int bj = bi + (t0 - (bi * NB - (bi * (bi - 1)) / 2));

    uint32_t sb = smem_u32(smem);
    int tid  = threadIdx.x;
    int lane = tid & 31;
    int wid  = tid >> 5;
    int wm = wid >> 1;          // 0..3 -> 32-row strip
    int wn = wid & 1;           // 0..1 -> 64-col strip
    int row0 = bi * BM, col0 = bj * BM;

    auto fill = [&](int s, int buf) {
        uint32_t base = sb + buf * BUF_BYTES;
        size_t kb = (size_t)s * (BK * 2);   // 128 bytes per step along k
#pragma unroll
        for (int p = 0; p < 4; p++) {
            int id  = tid + p * 256;        // 0..1023
            int row = id >> 3;
            int seg = id & 7;
            uint32_t soff = row * LDT + seg * 16;
            cp16(base + soff,
                 (const char*)(g_xb + (size_t)(row0 + row) * D) + kb + seg * 16);
            cp16(base + TILE_BYTES + soff,
                 (const char*)(g_xb + (size_t)(col0 + row) * D) + kb + seg * 16);
        }
    };

    float acc[2][8][4];
#pragma unroll
    for (int i = 0; i < 2; i++)
#pragma unroll
        for (int j = 0; j < 8; j++)
#pragma unroll
            for (int q = 0; q < 4; q++) acc[i][j][q] = 0.f;

    fill(0, 0); cp_commit();

    for (int s = 0; s < NSTEP; s++) {
        int buf = s & 1;
        cp_wait<0>();       // fill(s) complete (only group in flight)
        __syncthreads();    // all warps done with step s-1 reads of buf^1
        if (s + 1 < NSTEP) { fill(s + 1, buf ^ 1); cp_commit(); }

        uint32_t Ab = sb + buf * BUF_BYTES;
        uint32_t Bb = Ab + TILE_BYTES;
#pragma unroll
        for (int kh = 0; kh < 4; kh++) {
            int k0 = kh * 16;
            uint32_t af[2][4];
#pragma unroll
            for (int i = 0; i < 2; i++) {
                uint32_t addr = Ab + (wm * 32 + i * 16 + (lane & 15)) * LDT +
                                (k0 + (lane >> 4) * 8) * 2;
                ldm_x4(af[i][0], af[i][1], af[i][2], af[i][3], addr);
            }
            uint32_t bfr[8][2];
#pragma unroll
            for (int jp = 0; jp < 4; jp++) {
                int n0 = wn * 64 + jp * 16;
                uint32_t addr = Bb + (n0 + (lane & 7) + (lane >> 4) * 8) * LDT +
                                (k0 + ((lane >> 3) & 1) * 8) * 2;
                uint32_t b0, b1, b2, b3;
                ldm_x4(b0, b1, b2, b3, addr);
                bfr[jp * 2][0] = b0;     bfr[jp * 2][1] = b1;
                bfr[jp * 2 + 1][0] = b2; bfr[jp * 2 + 1][1] = b3;
            }
#pragma unroll
            for (int i = 0; i < 2; i++)
#pragma unroll
                for (int j = 0; j < 8; j++)
                    mma_bf16(acc[i][j], af[i], bfr[j]);
        }
    }

    // ---- epilogue: register-space dual argmax via packed-u64 shuffles ----
    // acc[i][j][h*2+q] -> row = wm*32+i*16+h*8+(lane>>2), col = wn*64+j*8+(lane&3)*2+q

    // row argmax (reduce over lane&3)
#pragma unroll
    for (int i = 0; i < 2; i++) {
#pragma unroll
        for (int h = 0; h < 2; h++) {
            int gi = row0 + wm * 32 + i * 16 + h * 8 + (lane >> 2);
            float bv = -2.f;
            int bc = 0;
#pragma unroll
            for (int j = 0; j < 8; j++) {
#pragma unroll
                for (int q = 0; q < 2; q++) {
                    int gj = col0 + wn * 64 + j * 8 + (lane & 3) * 2 + q;
                    float v = acc[i][j][h * 2 + q];
                    if (gj != gi && v > bv) { bv = v; bc = gj; }
                }
            }
            unsigned long long pk =
                ((unsigned long long)f2s(bv) << 32) |
                (unsigned long long)(0xFFFFFFFFu - (unsigned)bc);
            pk = pmax(pk, __shfl_xor_sync(0xffffffffu, pk, 1));
            pk = pmax(pk, __shfl_xor_sync(0xffffffffu, pk, 2));
            if ((lane & 3) == 0) atomicMax(&g_best[gi], pk);
        }
    }

    // col argmax (symmetry; reduce over lane>>2)
#pragma unroll
    for (int j = 0; j < 8; j++) {
#pragma unroll
        for (int q = 0; q < 2; q++) {
            int gj = col0 + wn * 64 + j * 8 + (lane & 3) * 2 + q;
            float bv = -2.f;
            int br = 0;
#pragma unroll
            for (int i = 0; i < 2; i++) {
#pragma unroll
                for (int h = 0; h < 2; h++) {
                    int gi = row0 + wm * 32 + i * 16 + h * 8 + (lane >> 2);
                    float v = acc[i][j][h * 2 + q];
                    if (gi != gj && v > bv) { bv = v; br = gi; }
                }
            }
            unsigned long long pk =
                ((unsigned long long)f2s(bv) << 32) |
                (unsigned long long)(0xFFFFFFFFu - (unsigned)br);
            pk = pmax(pk, __shfl_xor_sync(0xffffffffu, pk, 4));
            pk = pmax(pk, __shfl_xor_sync(0xffffffffu, pk, 8));
            pk = pmax(pk, __shfl_xor_sync(0xffffffffu, pk, 16));
            if ((lane >> 2) == 0) atomicMax(&g_best[gj], pk);
        }
    }
}

// ---------------------------------------------------------------------------
// Kernel 3: finalize. dist^2 = 2 - 2*dot (unit sphere); loss = -mean log(dist).
// ---------------------------------------------------------------------------
__global__ void __launch_bounds__(1024) finalize_kernel(float* __restrict__ out) {
    __shared__ float red[1024];
    int t = threadIdx.x;
    float s = 0.f;
#pragma unroll
    for (int p = 0; p < N / 1024; p++) {
        int i = t + p * 1024;
        unsigned hi = (unsigned)(g_best[i] >> 32);
        float dot = s2f(hi);
        float d2 = fmaxf(2.0f - 2.0f * dot, 0.0f);
        s += logf(sqrtf(d2) + 1e-8f);
    }
    red[t] = s;
    __syncthreads();
#pragma unroll
    for (int k = 512; k > 0; k >>= 1) {
        if (t < k) red[t] += red[t + k];
        __syncthreads();
    }
    if (t == 0) out[0] = -red[0] / (float)N;
}

extern "C" void kernel_launch(void* const* d_in, const int* in_sizes, int n_in,
                              void* d_out, int out_size) {
    const float* a = (const float*)d_in[0];
    const float* b = (const float*)d_in[1];
    float* out = (float*)d_out;

    cudaFuncSetAttribute(gemm_argmax_hmma,
                         cudaFuncAttributeMaxDynamicSharedMemorySize, SMEM_TOTAL);

    normalize_kernel<<<N / 8, 256>>>(a, b);

    gemm_argmax_hmma<<<NTILES, 256, SMEM_TOTAL>>>();

    finalize_kernel<<<1, 1024>>>(out);
}

// round 17
// speedup vs baseline: 1.0380x; 1.0380x over previous
#include <cuda_runtime.h>
#include <cuda_bf16.h>
#include <math.h>
#include <stdint.h>

#define N   16384
#define D   768
#define DH  384
#define BM  128
#define NB  (N / BM)                 // 128
#define NTILES (NB * (NB + 1) / 2)   // 8256
#define BK  64
#define NSTEP (D / BK)               // 12

// smem tile: 128 rows x 128 B data, pitch 144 B -> conflict-free ldmatrix
#define LDT 144
#define TILE_BYTES (128 * LDT)              // 18432
#define BUF_BYTES  (2 * TILE_BYTES)         // A+B = 36864
#define NSTAGE 2
#define SMEM_TOTAL (NSTAGE * BUF_BYTES)     // 73728

// ---- device globals (allocation-free scratch) ----
__device__ __nv_bfloat16      g_xb[(size_t)N * D];   // bf16 row-major (24 MB)
__device__ unsigned long long g_best[N];

__device__ __forceinline__ uint32_t smem_u32(const void* p) {
    uint32_t a;
    asm("{ .reg .u64 t; cvta.to.shared.u64 t, %1; cvt.u32.u64 %0, t; }" : "=r"(a) : "l"(p));
    return a;
}
__device__ __forceinline__ unsigned f2s(float f) {
    unsigned u = __float_as_uint(f);
    return u ^ ((u & 0x80000000u) ? 0xFFFFFFFFu : 0x80000000u);
}
__device__ __forceinline__ float s2f(unsigned s) {
    unsigned u = (s & 0x80000000u) ? (s ^ 0x80000000u) : ~s;
    return __uint_as_float(u);
}
__device__ __forceinline__ void cp16(uint32_t s, const void* g) {
    asm volatile("cp.async.ca.shared.global [%0], [%1], 16;" :: "r"(s), "l"(g) : "memory");
}
__device__ __forceinline__ void cp_commit() {
    asm volatile("cp.async.commit_group;" ::: "memory");
}
template <int K>
__device__ __forceinline__ void cp_wait() {
    asm volatile("cp.async.wait_group %0;" :: "n"(K) : "memory");
}
__device__ __forceinline__ void ldm_x4(uint32_t& r0, uint32_t& r1, uint32_t& r2, uint32_t& r3,
                                       uint32_t addr) {
    asm volatile("ldmatrix.sync.aligned.m8n8.x4.shared.b16 {%0,%1,%2,%3}, [%4];"
                 : "=r"(r0), "=r"(r1), "=r"(r2), "=r"(r3) : "r"(addr));
}
__device__ __forceinline__ void mma_bf16(float* d, const uint32_t* a, const uint32_t* b) {
    asm volatile(
        "mma.sync.aligned.m16n8k16.row.col.f32.bf16.bf16.f32 "
        "{%0,%1,%2,%3}, {%4,%5,%6,%7}, {%8,%9}, {%0,%1,%2,%3};"
        : "+f"(d[0]), "+f"(d[1]), "+f"(d[2]), "+f"(d[3])
        : "r"(a[0]), "r"(a[1]), "r"(a[2]), "r"(a[3]), "r"(b[0]), "r"(b[1]));
}
__device__ __forceinline__ unsigned long long pmax(unsigned long long a, unsigned long long b) {
    return a > b ? a : b;
}

// ---------------------------------------------------------------------------
// Kernel 1: concat + L2 normalize -> bf16 g_xb. One WARP per row, no barriers.
// ---------------------------------------------------------------------------
__global__ void __launch_bounds__(256) normalize_kernel(const float* __restrict__ a,
                                                        const float* __restrict__ b) {
    int lane = threadIdx.x & 31;
    int wid  = threadIdx.x >> 5;
    int r = blockIdx.x * 8 + wid;

    const float4* A = (const float4*)(a + (size_t)r * DH);
    const float4* B = (const float4*)(b + (size_t)r * DH);
    float4 va[3], vb[3];
    float ss = 0.f;
#pragma unroll
    for (int p = 0; p < 3; p++) {
        va[p] = A[lane + 32 * p];
        vb[p] = B[lane + 32 * p];
        ss += va[p].x * va[p].x + va[p].y * va[p].y +
              va[p].z * va[p].z + va[p].w * va[p].w;
        ss += vb[p].x * vb[p].x + vb[p].y * vb[p].y +
              vb[p].z * vb[p].z + vb[p].w * vb[p].w;
    }
#pragma unroll
    for (int o = 16; o > 0; o >>= 1)
        ss += __shfl_xor_sync(0xffffffffu, ss, o);
    float inv = 1.0f / fmaxf(sqrtf(ss), 1e-8f);

    uint2* dst = (uint2*)(g_xb + (size_t)r * D);   // 4 bf16 per uint2
#pragma unroll
    for (int p = 0; p < 3; p++) {
        uint2 u;
        __nv_bfloat162* ph = (__nv_bfloat162*)&u;
        ph[0] = __floats2bfloat162_rn(va[p].x * inv, va[p].y * inv);
        ph[1] = __floats2bfloat162_rn(va[p].z * inv, va[p].w * inv);
        dst[lane + 32 * p] = u;
        uint2 w;
        __nv_bfloat162* qh = (__nv_bfloat162*)&w;
        qh[0] = __floats2bfloat162_rn(vb[p].x * inv, vb[p].y * inv);
        qh[1] = __floats2bfloat162_rn(vb[p].z * inv, vb[p].w * inv);
        dst[96 + lane + 32 * p] = w;
    }
    if (lane == 0) g_best[r] = 0ull;
}

// ---------------------------------------------------------------------------
// Kernel 2: bf16 HMMA (f32 acc) 128x128x768 tile GEMM + fused dual argmax.
// 8 warps (32x64 per warp), BK=64, 2-stage, one barrier per k-step,
// 2 CTAs/SM, triangular grid, .ca fills (proven best).
// ---------------------------------------------------------------------------
__global__ void __launch_bounds__(256, 2) gemm_argmax_hmma() {
    extern __shared__ char smem[];

    // map linear tile id -> upper-triangle (bi, bj)
    int t0 = blockIdx.x;
    int bi = (int)floorf((2.0f * NB + 1.0f -
              sqrtf((2.0f * NB + 1.0f) * (2.0f * NB + 1.0f) - 8.0f * (float)t0)) * 0.5f);
    while ((bi + 1) * NB - ((bi + 1) * bi) / 2 <= t0) bi++;
    while (bi * NB - (bi * (bi - 1)) / 2 > t0) bi--;
    int bj = bi + (t0 - (bi * NB - (bi * (bi - 1)) / 2));

    uint32_t sb = smem_u32(smem);
    int tid  = threadIdx.x;
    int lane = tid & 31;
    int wid  = tid >> 5;
    int wm = wid >> 1;          // 0..3 -> 32-row strip
    int wn = wid & 1;           // 0..1 -> 64-col strip
    int row0 = bi * BM, col0 = bj * BM;

    auto fill = [&](int s, int buf) {
        uint32_t base = sb + buf * BUF_BYTES;
        size_t kb = (size_t)s * (BK * 2);   // 128 bytes per step along k
#pragma unroll
        for (int p = 0; p < 4; p++) {
            int id  = tid + p * 256;        // 0..1023
            int row = id >> 3;
            int seg = id & 7;
            uint32_t soff = row * LDT + seg * 16;
            cp16(base + soff,
                 (const char*)(g_xb + (size_t)(row0 + row) * D) + kb + seg * 16);
            cp16(base + TILE_BYTES + soff,
                 (const char*)(g_xb + (size_t)(col0 + row) * D) + kb + seg * 16);
        }
    };

    float acc[2][8][4];
#pragma unroll
    for (int i = 0; i < 2; i++)
#pragma unroll
        for (int j = 0; j < 8; j++)
#pragma unroll
            for (int q = 0; q < 4; q++) acc[i][j][q] = 0.f;

    fill(0, 0); cp_commit();

    for (int s = 0; s < NSTEP; s++) {
        int buf = s & 1;
        cp_wait<0>();       // fill(s) complete (only group in flight)
        __syncthreads();    // all warps done with step s-1 reads of buf^1
        if (s + 1 < NSTEP) { fill(s + 1, buf ^ 1); cp_commit(); }

        uint32_t Ab = sb + buf * BUF_BYTES;
        uint32_t Bb = Ab + TILE_BYTES;
#pragma unroll
        for (int kh = 0; kh < 4; kh++) {
            int k0 = kh * 16;
            uint32_t af[2][4];
#pragma unroll
            for (int i = 0; i < 2; i++) {
                uint32_t addr = Ab + (wm * 32 + i * 16 + (lane & 15)) * LDT +
                                (k0 + (lane >> 4) * 8) * 2;
                ldm_x4(af[i][0], af[i][1], af[i][2], af[i][3], addr);
            }
            uint32_t bfr[8][2];
#pragma unroll
            for (int jp = 0; jp < 4; jp++) {
                int n0 = wn * 64 + jp * 16;
                uint32_t addr = Bb + (n0 + (lane & 7) + (lane >> 4) * 8) * LDT +
                                (k0 + ((lane >> 3) & 1) * 8) * 2;
                uint32_t b0, b1, b2, b3;
                ldm_x4(b0, b1, b2, b3, addr);
                bfr[jp * 2][0] = b0;     bfr[jp * 2][1] = b1;
                bfr[jp * 2 + 1][0] = b2; bfr[jp * 2 + 1][1] = b3;
            }
#pragma unroll
            for (int i = 0; i < 2; i++)
#pragma unroll
                for (int j = 0; j < 8; j++)
                    mma_bf16(acc[i][j], af[i], bfr[j]);
        }
    }

    // ---- epilogue: register-space dual argmax via packed-u64 shuffles ----
    // acc[i][j][h*2+q] -> row = wm*32+i*16+h*8+(lane>>2), col = wn*64+j*8+(lane&3)*2+q

    // row argmax (reduce over lane&3)
#pragma unroll
    for (int i = 0; i < 2; i++) {
#pragma unroll
        for (int h = 0; h < 2; h++) {
            int gi = row0 + wm * 32 + i * 16 + h * 8 + (lane >> 2);
            float bv = -2.f;
            int bc = 0;
#pragma unroll
            for (int j = 0; j < 8; j++) {
#pragma unroll
                for (int q = 0; q < 2; q++) {
                    int gj = col0 + wn * 64 + j * 8 + (lane & 3) * 2 + q;
                    float v = acc[i][j][h * 2 + q];
                    if (gj != gi && v > bv) { bv = v; bc = gj; }
                }
            }
            unsigned long long pk =
                ((unsigned long long)f2s(bv) << 32) |
                (unsigned long long)(0xFFFFFFFFu - (unsigned)bc);
            pk = pmax(pk, __shfl_xor_sync(0xffffffffu, pk, 1));
            pk = pmax(pk, __shfl_xor_sync(0xffffffffu, pk, 2));
            if ((lane & 3) == 0) atomicMax(&g_best[gi], pk);
        }
    }

    // col argmax (symmetry; reduce over lane>>2)
#pragma unroll
    for (int j = 0; j < 8; j++) {
#pragma unroll
        for (int q = 0; q < 2; q++) {
            int gj = col0 + wn * 64 + j * 8 + (lane & 3) * 2 + q;
            float bv = -2.f;
            int br = 0;
#pragma unroll
            for (int i = 0; i < 2; i++) {
#pragma unroll
                for (int h = 0; h < 2; h++) {
                    int gi = row0 + wm * 32 + i * 16 + h * 8 + (lane >> 2);
                    float v = acc[i][j][h * 2 + q];
                    if (gi != gj && v > bv) { bv = v; br = gi; }
                }
            }
            unsigned long long pk =
                ((unsigned long long)f2s(bv) << 32) |
                (unsigned long long)(0xFFFFFFFFu - (unsigned)br);
            pk = pmax(pk, __shfl_xor_sync(0xffffffffu, pk, 4));
            pk = pmax(pk, __shfl_xor_sync(0xffffffffu, pk, 8));
            pk = pmax(pk, __shfl_xor_sync(0xffffffffu, pk, 16));
            if ((lane >> 2) == 0) atomicMax(&g_best[gj], pk);
        }
    }
}

// ---------------------------------------------------------------------------
// Kernel 3: finalize. dist^2 = 2 - 2*dot (unit sphere); loss = -mean log(dist).
// ---------------------------------------------------------------------------
__global__ void __launch_bounds__(1024) finalize_kernel(float* __restrict__ out) {
    __shared__ float red[1024];
    int t = threadIdx.x;
    float s = 0.f;
#pragma unroll
    for (int p = 0; p < N / 1024; p++) {
        int i = t + p * 1024;
        unsigned hi = (unsigned)(g_best[i] >> 32);
        float dot = s2f(hi);
        float d2 = fmaxf(2.0f - 2.0f * dot, 0.0f);
        s += logf(sqrtf(d2) + 1e-8f);
    }
    red[t] = s;
    __syncthreads();
#pragma unroll
    for (int k = 512; k > 0; k >>= 1) {
        if (t < k) red[t] += red[t + k];
        __syncthreads();
    }
    if (t == 0) out[0] = -red[0] / (float)N;
}

extern "C" void kernel_launch(void* const* d_in, const int* in_sizes, int n_in,
                              void* d_out, int out_size) {
    const float* a = (const float*)d_in[0];
    const float* b = (const float*)d_in[1];
    float* out = (float*)d_out;

    cudaFuncSetAttribute(gemm_argmax_hmma,
                         cudaFuncAttributeMaxDynamicSharedMemorySize, SMEM_TOTAL);

    normalize_kernel<<<N / 8, 256>>>(a, b);

    gemm_argmax_hmma<<<NTILES, 256, SMEM_TOTAL>>>();

    finalize_kernel<<<1, 1024>>>(out);
}